// round 16
// baseline (speedup 1.0000x reference)
#include <cuda_runtime.h>
#include <cuda_bf16.h>
#include <cstdint>

#define NAB 768
#define NY  512
#define NCOL (NAB * NAB)          // 589824
#define CLUSTER 16
#define RPC (NAB / CLUSTER)       // 48 rows/cols per CTA
#define THREADS 768
#define MAX_ITERS 500
#define TOL 1e-6f

// dynamic smem layout (bytes). sTf rows padded to 49 floats (conflict-free).
#define STF_PAD 49
#define SKR_BYTES (RPC * NAB * 2)         // 73728: my 48 rows, bf16
#define SKC_BYTES (NAB * RPC * 2)         // 73728: my 48 cols (transposed), bf16
#define STF_BYTES (64 * STF_PAD * 4)      // 12544: T-phase partials
#define DYN_BYTES (SKR_BYTES + SKC_BYTES + STF_BYTES)   // 160000

#define AF_TX 3072u                        // 768 values * 4B per phase
#define BF_TX 3072u

// Scratch (no allocations allowed)
__device__ float g_AF[NAB];
__device__ float g_BF[NAB];
__device__ float g_part[NY * NAB];

__device__ __forceinline__ void cluster_arrive_wait() {
    asm volatile("barrier.cluster.arrive.aligned;" ::: "memory");
    asm volatile("barrier.cluster.wait.aligned;"   ::: "memory");
}
__device__ __forceinline__ uint32_t mapa_sh(uint32_t laddr, int rank) {
    uint32_t ra;
    asm("mapa.shared::cluster.u32 %0, %1, %2;" : "=r"(ra) : "r"(laddr), "r"(rank));
    return ra;
}
__device__ __forceinline__ void st_cl_f32(uint32_t raddr, float v) {
    asm volatile("st.shared::cluster.f32 [%0], %1;" :: "r"(raddr), "f"(v) : "memory");
}
__device__ __forceinline__ void st_cl_u32(uint32_t raddr, unsigned v) {
    asm volatile("st.shared::cluster.u32 [%0], %1;" :: "r"(raddr), "r"(v) : "memory");
}
// push an 8B pair straight from registers; completes 8 tx bytes remotely
__device__ __forceinline__ void st_async_f2(uint32_t raddr, float a, float b,
                                            uint32_t rmbar) {
    const uint64_t v = (uint64_t)__float_as_uint(a) |
                       ((uint64_t)__float_as_uint(b) << 32);
    asm volatile("st.async.shared::cluster.mbarrier::complete_tx::bytes.b64 "
                 "[%0], %1, [%2];"
                 :: "r"(raddr), "l"(v), "r"(rmbar) : "memory");
}
__device__ __forceinline__ void mbar_init(uint32_t mbar, uint32_t count) {
    asm volatile("mbarrier.init.shared.b64 [%0], %1;" :: "r"(mbar), "r"(count) : "memory");
}
__device__ __forceinline__ void mbar_expect_tx(uint32_t mbar, uint32_t bytes) {
    asm volatile("mbarrier.arrive.expect_tx.shared.b64 _, [%0], %1;"
                 :: "r"(mbar), "r"(bytes) : "memory");
}
__device__ __forceinline__ void mbar_wait_par(uint32_t mbar, uint32_t parity) {
    uint32_t done;
    asm volatile("{\n\t.reg .pred p;\n\t"
        "mbarrier.try_wait.parity.acquire.cluster.shared::cta.b64 p, [%1], %2;\n\t"
        "selp.b32 %0, 1, 0, p;\n\t}"
        : "=r"(done) : "r"(mbar), "r"(parity) : "memory");
    while (!done) {
        asm volatile("{\n\t.reg .pred p;\n\t"
            "mbarrier.try_wait.parity.acquire.cluster.shared::cta.b64 p, [%1], %2, 0x989680;\n\t"
            "selp.b32 %0, 1, 0, p;\n\t}"
            : "=r"(done) : "r"(mbar), "r"(parity) : "memory");
    }
}
__device__ __forceinline__ float2 bf2f(uint32_t u) {
    return __bfloat1622float2(*reinterpret_cast<__nv_bfloat162*>(&u));
}

// ---------------------------------------------------------------------------
// Solve: 16-CTA cluster, bf16 K in SMEM, Aitken cadence-4 (R7 optimum).
// NEW: warp-autonomous exchange — each warp pushes its own 2 values straight
// from registers via st.async.b64 to all 16 ranks the moment it finishes
// (no staging barriers; skew-pipelined). 2 fewer __syncthreads/iteration.
// Stops on provable max|dC| <= 1e-6; final differentiable iterate on f32 K.
// ---------------------------------------------------------------------------
__global__ void __launch_bounds__(THREADS, 1)
solve_kernel(const float* __restrict__ AT, const float* __restrict__ BT,
             const float* __restrict__ K)
{
    extern __shared__ __align__(16) char dyn[];
    __nv_bfloat16* sKr = (__nv_bfloat16*)dyn;                    // [48][768]
    __nv_bfloat16* sKc = (__nv_bfloat16*)(dyn + SKR_BYTES);      // [768][48]
    float*         sTf = (float*)(dyn + SKR_BYTES + SKC_BYTES);  // [64][49]

    __shared__ __align__(16) float sAF[NAB];
    __shared__ __align__(16) float sBF[NAB];
    __shared__ float sR[6][24];                 // per-warp stat partials
    __shared__ float sFin[6];                   // dA,dB,mA,mB,pn,pd
    __shared__ unsigned sKm[CLUSTER];
    __shared__ unsigned sKloc;
    __shared__ __align__(8) unsigned long long mbAF_s, mbEx_s;

    const int tid  = threadIdx.x;
    int crank;
    asm("mov.u32 %0, %%cluster_ctarank;" : "=r"(crank));
    const int base = crank * RPC;
    const int lane = tid & 31;
    const int warp = tid >> 5;                 // 24 warps
    const int cq   = tid % 12;                 // T-phase column quad (48 cols)
    const int gg0  = tid / 12;                 // T-phase row group (64 groups)

    const uint32_t mbAF = (uint32_t)__cvta_generic_to_shared(&mbAF_s);
    const uint32_t mbEx = (uint32_t)__cvta_generic_to_shared(&mbEx_s);
    if (tid == 0) { mbar_init(mbAF, 1); mbar_init(mbEx, 1); sKloc = 0u; }

    sAF[tid] = AT[tid];
    sBF[tid] = BT[tid];

    // ---- preamble: K slices -> bf16 SMEM; local maxK ----
    {
        float km = 0.f;
        for (int idx = tid; idx < RPC * NAB; idx += THREADS) {
            const float v = K[(size_t)(base + idx / NAB) * NAB + (idx % NAB)];
            km = fmaxf(km, v);
            sKr[idx] = __float2bfloat16(v);
        }
        atomicMax(&sKloc, __float_as_uint(km));
        for (int idx = tid; idx < NAB * RPC; idx += THREADS) {
            const int i = idx / RPC, jl = idx % RPC;
            sKc[i * RPC + jl] = __float2bfloat16(K[(size_t)i * NAB + base + jl]);
        }
    }
    __syncthreads();
    // exchange local maxK; cluster barrier also publishes mbarrier init
    if (tid < CLUSTER)
        st_cl_u32(mapa_sh((uint32_t)__cvta_generic_to_shared(&sKm[crank]), tid), sKloc);
    cluster_arrive_wait();
    float kmax = 0.f;
    #pragma unroll
    for (int r = 0; r < CLUSTER; ++r) kmax = fmaxf(kmax, __uint_as_float(sKm[r]));

    // ---- warp-autonomous send addresses: lane l<16 targets rank l ----
    const int r0 = base + warp * 2;            // my warp's 2 rows/cols
    uint32_t rAF2 = 0, rBF2 = 0, rMbA2 = 0, rMbE2 = 0;
    if (lane < 16) {
        rAF2  = mapa_sh((uint32_t)__cvta_generic_to_shared(&sAF[r0]), lane);
        rBF2  = mapa_sh((uint32_t)__cvta_generic_to_shared(&sBF[r0]), lane);
        rMbA2 = mapa_sh(mbAF, lane);
        rMbE2 = mapa_sh(mbEx, lane);
    }

    // totals loaded in ALL lanes (broadcast loads) so every sender lane has them
    const float at0 = AT[r0],       at1 = AT[r0 + 1];
    const float bt0 = BT[r0],       bt1 = BT[r0 + 1];

    // Aitken state (per-thread, identical across CTAs)
    float afp = sAF[tid], bfp = sBF[tid];
    float doaf = 0.f, dobf = 0.f;
    bool  have = false;
    int   ph   = 0;

    for (int iter = 0; iter < MAX_ITERS; ++iter) {
        const uint32_t par = iter & 1;
        if (tid == 0) { mbar_expect_tx(mbAF, AF_TX); mbar_expect_tx(mbEx, BF_TX); }

        // ---------------- S phase: AF = AT / (1 + K @ BF), bf16 SMEM ------
        float s0 = 0.f, s1 = 0.f;
        {
            const uint2* kr0 = (const uint2*)sKr + (size_t)(warp * 2) * 192;
            const uint2* kr1 = kr0 + 192;
            const float4* bf4 = (const float4*)sBF;
            #pragma unroll
            for (int t = 0; t < 6; ++t) {
                const int ix = lane + 32 * t;
                const uint2 u0 = kr0[ix];
                const uint2 u1 = kr1[ix];
                const float4 bv = bf4[ix];
                const float2 a0 = bf2f(u0.x), a1 = bf2f(u0.y);
                const float2 b0 = bf2f(u1.x), b1 = bf2f(u1.y);
                s0 += a0.x*bv.x + a0.y*bv.y + a1.x*bv.z + a1.y*bv.w;
                s1 += b0.x*bv.x + b0.y*bv.y + b1.x*bv.z + b1.y*bv.w;
            }
        }
        #pragma unroll
        for (int o = 16; o; o >>= 1) {
            s0 += __shfl_down_sync(0xffffffffu, s0, o);
            s1 += __shfl_down_sync(0xffffffffu, s1, o);
        }
        s0 = __shfl_sync(0xffffffffu, s0, 0);
        s1 = __shfl_sync(0xffffffffu, s1, 0);
        {   // every sender lane computes the same 2 AF values; push to 16 ranks
            const float af0 = at0 / (1.f + s0);
            const float af1 = at1 / (1.f + s1);
            if (lane < 16) st_async_f2(rAF2, af0, af1, rMbA2);   // no barrier!
        }
        mbar_wait_par(mbAF, par);               // full AF now in sAF
        const float afc = sAF[tid];             // capture BEFORE any BF send

        // ---------------- T phase: BF = BT / (1 + K^T @ AF), bf16 SMEM ----
        float4 acc = make_float4(0.f, 0.f, 0.f, 0.f);
        #pragma unroll
        for (int t = 0; t < 12; ++t) {
            const int i = gg0 + 64 * t;
            const uint2 u = *(const uint2*)(sKc + i * RPC + cq * 4);
            const float a = sAF[i];
            const float2 f0 = bf2f(u.x), f1 = bf2f(u.y);
            acc.x += f0.x * a; acc.y += f0.y * a;
            acc.z += f1.x * a; acc.w += f1.y * a;
        }
        {
            const int tb = gg0 * STF_PAD + cq * 4;
            sTf[tb]     = acc.x; sTf[tb + 1] = acc.y;
            sTf[tb + 2] = acc.z; sTf[tb + 3] = acc.w;
        }
        __syncthreads();
        {   // warp-per-2-columns reduction, then warp-autonomous BF push
            const int c0 = warp * 2, c1 = c0 + 1;
            float t0 = sTf[lane * STF_PAD + c0] + sTf[(lane + 32) * STF_PAD + c0];
            float t1 = sTf[lane * STF_PAD + c1] + sTf[(lane + 32) * STF_PAD + c1];
            #pragma unroll
            for (int o = 16; o; o >>= 1) {
                t0 += __shfl_down_sync(0xffffffffu, t0, o);
                t1 += __shfl_down_sync(0xffffffffu, t1, o);
            }
            t0 = __shfl_sync(0xffffffffu, t0, 0);
            t1 = __shfl_sync(0xffffffffu, t1, 0);
            const float bf0 = bt0 / (1.f + t0);
            const float bf1 = bt1 / (1.f + t1);
            if (lane < 16) st_async_f2(rBF2, bf0, bf1, rMbE2);   // no barrier!
        }
        mbar_wait_par(mbEx, par);               // full BF now in sBF
        const float bfc = sBF[tid];

        // per-thread deltas every iteration (cheap, no reduction)
        const float dnaf = afc - afp, dnbf = bfc - bfp;

        if (par) {
            // ---- odd iters only: redundant deterministic stats + lambda ----
            float dA = fabsf(dnaf), dB = fabsf(dnbf), mA = afc, mB = bfc;
            float pn = 0.f, pd = 0.f;
            if (have) { pn = dnaf*doaf + dnbf*dobf; pd = doaf*doaf + dobf*dobf; }
            #pragma unroll
            for (int o = 16; o; o >>= 1) {
                dA = fmaxf(dA, __shfl_down_sync(0xffffffffu, dA, o));
                dB = fmaxf(dB, __shfl_down_sync(0xffffffffu, dB, o));
                mA = fmaxf(mA, __shfl_down_sync(0xffffffffu, mA, o));
                mB = fmaxf(mB, __shfl_down_sync(0xffffffffu, mB, o));
                pn += __shfl_down_sync(0xffffffffu, pn, o);
                pd += __shfl_down_sync(0xffffffffu, pd, o);
            }
            if (lane == 0) {
                sR[0][warp] = dA; sR[1][warp] = dB; sR[2][warp] = mA;
                sR[3][warp] = mB; sR[4][warp] = pn; sR[5][warp] = pd;
            }
            __syncthreads();
            if (warp < 6) {
                float v = (lane < 24) ? sR[warp][lane] : 0.f;
                if (warp < 4) {
                    #pragma unroll
                    for (int o = 16; o; o >>= 1) v = fmaxf(v, __shfl_down_sync(0xffffffffu, v, o));
                } else {
                    #pragma unroll
                    for (int o = 16; o; o >>= 1) v += __shfl_down_sync(0xffffffffu, v, o);
                }
                if (lane == 0) sFin[warp] = v;
            }
            __syncthreads();
            const float gdA = sFin[0], gdB = sFin[1], gmA = sFin[2], gmB = sFin[3];
            const float lam = (sFin[5] > 1e-30f) ? (sFin[4] / sFin[5]) : 2.f;
            const float bound = kmax * (gdA * gmB + (gmA + gdA) * gdB);
            if (bound <= TOL) break;

            // measured-optimal cadence (R7): ext every 4th iteration
            const bool doExt = have && (ph >= 2) && (lam > -0.9f) && (lam < 0.97f);
            if (doExt) {
                const float f = fminf(lam / (1.f - lam), 32.f);
                const float nb = fmaxf(bfc + dnbf * f, 0.f);
                sBF[tid] = nb;                  // only BF propagates (GS structure)
                afp = fmaxf(afc + dnaf * f, 0.f);
                bfp = nb;
                have = false; ph = 0;
                __syncthreads();
                continue;
            }
        }
        afp = afc; bfp = bfc;
        doaf = dnaf; dobf = dnbf;
        have = true; ++ph;
    }

    // ---------------- final differentiable iterate on exact f32 K ----------
    {
        const float* Kr = K + (size_t)r0 * NAB;
        const float* Kc = K + base + cq * 4;
        const int brow  = tid >> 4;
        const int brnk  = tid & 15;
        const uint32_t rAFf = mapa_sh((uint32_t)__cvta_generic_to_shared(&sAF[base + brow]), brnk);

        float s0 = 0.f, s1 = 0.f;
        const float4* bf4 = (const float4*)sBF;
        #pragma unroll
        for (int t = 0; t < 6; ++t) {
            const int ix = lane + 32 * t;
            const float4 bv = bf4[ix];
            const float4 k0 = ((const float4*)(Kr      ))[ix];
            const float4 k1 = ((const float4*)(Kr + NAB))[ix];
            s0 += k0.x*bv.x + k0.y*bv.y + k0.z*bv.z + k0.w*bv.w;
            s1 += k1.x*bv.x + k1.y*bv.y + k1.z*bv.z + k1.w*bv.w;
        }
        #pragma unroll
        for (int o = 16; o; o >>= 1) {
            s0 += __shfl_down_sync(0xffffffffu, s0, o);
            s1 += __shfl_down_sync(0xffffffffu, s1, o);
        }
        if (lane == 0) {
            sAF[r0]     = at0 / (1.f + s0);
            sAF[r0 + 1] = at1 / (1.f + s1);
        }
        __syncthreads();
        st_cl_f32(rAFf, sAF[base + brow]);     // broadcast final AF
        cluster_arrive_wait();

        float4 acc = make_float4(0.f, 0.f, 0.f, 0.f);
        #pragma unroll
        for (int t = 0; t < 12; ++t) {
            const int i = gg0 + 64 * t;
            const float4 kv = *(const float4*)(Kc + (size_t)i * NAB);
            const float a = sAF[i];
            acc.x += kv.x * a; acc.y += kv.y * a;
            acc.z += kv.z * a; acc.w += kv.w * a;
        }
        {
            const int tb = gg0 * STF_PAD + cq * 4;
            sTf[tb]     = acc.x; sTf[tb + 1] = acc.y;
            sTf[tb + 2] = acc.z; sTf[tb + 3] = acc.w;
        }
        __syncthreads();
        {
            const int c0 = warp * 2, c1 = c0 + 1;
            float t0 = sTf[lane * STF_PAD + c0] + sTf[(lane + 32) * STF_PAD + c0];
            float t1 = sTf[lane * STF_PAD + c1] + sTf[(lane + 32) * STF_PAD + c1];
            #pragma unroll
            for (int o = 16; o; o >>= 1) {
                t0 += __shfl_down_sync(0xffffffffu, t0, o);
                t1 += __shfl_down_sync(0xffffffffu, t1, o);
            }
            if (lane == 0) {
                g_BF[base + c0] = bt0 / (1.f + t0);
                g_BF[base + c1] = bt1 / (1.f + t1);
            }
        }
        if (tid < RPC) g_AF[base + tid] = sAF[base + tid];
    }
}

// ---------------------------------------------------------------------------
// GEMV (768 blocks x 256 thr — measured ~7.3 TB/s, the HBM ceiling).
// ---------------------------------------------------------------------------
__global__ void __launch_bounds__(256)
gemv_kernel(const float* __restrict__ K, const float* __restrict__ W)
{
    __shared__ __align__(16) float sc[NAB];
    const int i    = blockIdx.x;
    const int tid  = threadIdx.x;
    const int lane = tid & 31;
    const int w    = tid >> 5;

    const float afi = g_AF[i];
    #pragma unroll
    for (int j = tid; j < NAB; j += 256)
        sc[j] = K[(size_t)i * NAB + j] * afi * g_BF[j];
    __syncthreads();

    const float4* sc4 = (const float4*)sc;
    const float*  Wb  = W + (size_t)i * NAB;
    for (int r = w; r < NY; r += 8) {
        const float4* wr = (const float4*)(Wb + (size_t)r * NCOL);
        float s = 0.f;
        #pragma unroll
        for (int t = 0; t < 6; ++t) {
            const float4 wv = __ldcs(&wr[lane + 32 * t]);
            const float4 cv = sc4[lane + 32 * t];
            s += wv.x * cv.x; s += wv.y * cv.y;
            s += wv.z * cv.z; s += wv.w * cv.w;
        }
        #pragma unroll
        for (int o = 16; o; o >>= 1) s += __shfl_down_sync(0xffffffffu, s, o);
        if (lane == 0) g_part[(size_t)r * NAB + i] = s;
    }
}

// ---------------------------------------------------------------------------
// Reduce: 64 blocks x 256 thr = 512 warps, one warp per output k.
// ---------------------------------------------------------------------------
__global__ void __launch_bounds__(256)
reduce_kernel(const float* __restrict__ b, float* __restrict__ Y)
{
    const int lane = threadIdx.x & 31;
    const int k    = blockIdx.x * 8 + (threadIdx.x >> 5);   // 512 warps = NY
    const float* p = &g_part[(size_t)k * NAB];
    float s = 0.f;
    #pragma unroll
    for (int t = 0; t < 24; ++t) s += p[lane + 32 * t];
    #pragma unroll
    for (int o = 16; o; o >>= 1) s += __shfl_down_sync(0xffffffffu, s, o);
    if (lane == 0) Y[k] = s + b[k];
}

extern "C" void kernel_launch(void* const* d_in, const int* in_sizes, int n_in,
                              void* d_out, int out_size)
{
    const float* AT = (const float*)d_in[0];
    const float* BT = (const float*)d_in[1];
    const float* K  = (const float*)d_in[2];
    const float* W  = (const float*)d_in[3];
    const float* b  = (const float*)d_in[4];
    float* Y = (float*)d_out;

    static int attr_done = 0;
    if (!attr_done) {
        cudaFuncSetAttribute((const void*)solve_kernel,
                             cudaFuncAttributeNonPortableClusterSizeAllowed, 1);
        cudaFuncSetAttribute((const void*)solve_kernel,
                             cudaFuncAttributeMaxDynamicSharedMemorySize, DYN_BYTES);
        attr_done = 1;
    }

    // solve: 16-CTA cluster
    cudaLaunchConfig_t cfg = {};
    cfg.gridDim  = {CLUSTER, 1, 1};
    cfg.blockDim = {THREADS, 1, 1};
    cfg.dynamicSmemBytes = DYN_BYTES;
    cfg.stream = 0;
    cudaLaunchAttribute at[1];
    at[0].id = cudaLaunchAttributeClusterDimension;
    at[0].val.clusterDim = {CLUSTER, 1, 1};
    cfg.attrs = at;
    cfg.numAttrs = 1;
    cudaLaunchKernelEx(&cfg, solve_kernel, AT, BT, K);

    gemv_kernel<<<NAB, 256>>>(K, W);
    reduce_kernel<<<64, 256>>>(b, Y);
}

// round 17
// speedup vs baseline: 1.0192x; 1.0192x over previous
#include <cuda_runtime.h>
#include <cuda_bf16.h>
#include <cstdint>

#define NAB 768
#define NY  512
#define NCOL (NAB * NAB)          // 589824
#define CLUSTER 16
#define RPC (NAB / CLUSTER)       // 48 rows/cols per CTA
#define THREADS 768
#define MAX_ITERS 500
#define TOL 1e-6f

// dynamic smem layout (bytes)
#define SKR_BYTES (RPC * NAB * 2)         // 73728: my 48 rows, bf16
#define SKC_BYTES (NAB * RPC * 2)         // 73728: my 48 cols (transposed), bf16
#define STF_BYTES (64 * RPC * 4)          // 12288: T-phase partials
#define ST2_BYTES (16 * RPC * 4)          //  3072: stage-2 partials
#define DYN_BYTES (SKR_BYTES + SKC_BYTES + STF_BYTES + ST2_BYTES)

#define AF_TX 3072u                        // 768 values * 4B per phase
#define BF_TX 3072u

// Scratch (no allocations allowed)
__device__ float g_AF[NAB];
__device__ float g_BF[NAB];
__device__ float g_part[NY * NAB];

__device__ __forceinline__ void cluster_arrive_wait() {
    asm volatile("barrier.cluster.arrive.aligned;" ::: "memory");
    asm volatile("barrier.cluster.wait.aligned;"   ::: "memory");
}
__device__ __forceinline__ uint32_t mapa_sh(uint32_t laddr, int rank) {
    uint32_t ra;
    asm("mapa.shared::cluster.u32 %0, %1, %2;" : "=r"(ra) : "r"(laddr), "r"(rank));
    return ra;
}
__device__ __forceinline__ void st_cl_f32(uint32_t raddr, float v) {
    asm volatile("st.shared::cluster.f32 [%0], %1;" :: "r"(raddr), "f"(v) : "memory");
}
__device__ __forceinline__ void st_cl_u32(uint32_t raddr, unsigned v) {
    asm volatile("st.shared::cluster.u32 [%0], %1;" :: "r"(raddr), "r"(v) : "memory");
}
__device__ __forceinline__ void st_async_v4(uint32_t raddr, uint4 v, uint32_t rmbar) {
    asm volatile("st.async.shared::cluster.mbarrier::complete_tx::bytes.v4.b32 "
                 "[%0], {%1,%2,%3,%4}, [%5];"
                 :: "r"(raddr), "r"(v.x), "r"(v.y), "r"(v.z), "r"(v.w), "r"(rmbar)
                 : "memory");
}
__device__ __forceinline__ void mbar_init(uint32_t mbar, uint32_t count) {
    asm volatile("mbarrier.init.shared.b64 [%0], %1;" :: "r"(mbar), "r"(count) : "memory");
}
__device__ __forceinline__ void mbar_expect_tx(uint32_t mbar, uint32_t bytes) {
    asm volatile("mbarrier.arrive.expect_tx.shared.b64 _, [%0], %1;"
                 :: "r"(mbar), "r"(bytes) : "memory");
}
__device__ __forceinline__ void mbar_wait_par(uint32_t mbar, uint32_t parity) {
    uint32_t done;
    asm volatile("{\n\t.reg .pred p;\n\t"
        "mbarrier.try_wait.parity.acquire.cluster.shared::cta.b64 p, [%1], %2;\n\t"
        "selp.b32 %0, 1, 0, p;\n\t}"
        : "=r"(done) : "r"(mbar), "r"(parity) : "memory");
    while (!done) {
        asm volatile("{\n\t.reg .pred p;\n\t"
            "mbarrier.try_wait.parity.acquire.cluster.shared::cta.b64 p, [%1], %2, 0x989680;\n\t"
            "selp.b32 %0, 1, 0, p;\n\t}"
            : "=r"(done) : "r"(mbar), "r"(parity) : "memory");
    }
}
__device__ __forceinline__ float2 bf2f(uint32_t u) {
    return __bfloat1622float2(*reinterpret_cast<__nv_bfloat162*>(&u));
}

// ---------------------------------------------------------------------------
// Solve (champion config, R7): one 16-CTA cluster, bf16 K in SMEM, v4
// st.async exchange (12 pkts x 16 ranks per phase) + mbarrier tx accounting.
// Aitken extrapolation at the measured-optimal cadence (ph>=2); stats and
// lambda reductions only on odd iterations. Stops on the provable
// max|dC| <= 1e-6 bound; final differentiable iterate on exact f32 K.
// ---------------------------------------------------------------------------
__global__ void __launch_bounds__(THREADS, 1)
solve_kernel(const float* __restrict__ AT, const float* __restrict__ BT,
             const float* __restrict__ K)
{
    extern __shared__ __align__(16) char dyn[];
    __nv_bfloat16* sKr = (__nv_bfloat16*)dyn;                    // [48][768]
    __nv_bfloat16* sKc = (__nv_bfloat16*)(dyn + SKR_BYTES);      // [768][48]
    float*         sTf = (float*)(dyn + SKR_BYTES + SKC_BYTES);  // [64][48]
    float*         sT2 = (float*)(dyn + SKR_BYTES + SKC_BYTES + STF_BYTES); // [16][48]

    __shared__ __align__(16) float sAF[NAB];
    __shared__ __align__(16) float sBF[NAB];
    __shared__ float sR[6][24];                 // per-warp stat partials
    __shared__ float sFin[6];                   // dA,dB,mA,mB,pn,pd
    __shared__ unsigned sKm[CLUSTER];
    __shared__ unsigned sKloc;
    __shared__ __align__(8) unsigned long long mbAF_s, mbEx_s;

    const int tid  = threadIdx.x;
    int crank;
    asm("mov.u32 %0, %%cluster_ctarank;" : "=r"(crank));
    const int base = crank * RPC;
    const int lane = tid & 31;
    const int warp = tid >> 5;                 // 24 warps
    const int cq   = tid % 12;                 // T-phase column quad (48 cols)
    const int gg0  = tid / 12;                 // T-phase row group (64 groups)

    if (tid == 0) cudaTriggerProgrammaticLaunchCompletion();

    const uint32_t mbAF = (uint32_t)__cvta_generic_to_shared(&mbAF_s);
    const uint32_t mbEx = (uint32_t)__cvta_generic_to_shared(&mbEx_s);
    if (tid == 0) { mbar_init(mbAF, 1); mbar_init(mbEx, 1); sKloc = 0u; }

    sAF[tid] = AT[tid];
    sBF[tid] = BT[tid];

    // ---- preamble: K slices -> bf16 SMEM; local maxK ----
    {
        float km = 0.f;
        for (int idx = tid; idx < RPC * NAB; idx += THREADS) {
            const float v = K[(size_t)(base + idx / NAB) * NAB + (idx % NAB)];
            km = fmaxf(km, v);
            sKr[idx] = __float2bfloat16(v);
        }
        atomicMax(&sKloc, __float_as_uint(km));
        for (int idx = tid; idx < NAB * RPC; idx += THREADS) {
            const int i = idx / RPC, jl = idx % RPC;
            sKc[i * RPC + jl] = __float2bfloat16(K[(size_t)i * NAB + base + jl]);
        }
    }
    __syncthreads();
    // exchange local maxK; cluster barrier also publishes mbarrier init
    if (tid < CLUSTER)
        st_cl_u32(mapa_sh((uint32_t)__cvta_generic_to_shared(&sKm[crank]), tid), sKloc);
    cluster_arrive_wait();
    float kmax = 0.f;
    #pragma unroll
    for (int r = 0; r < CLUSTER; ++r) kmax = fmaxf(kmax, __uint_as_float(sKm[r]));

    // ---- stable remote addresses: 192 sender threads, one v4 pkt each ----
    const int r0 = base + warp * 2;            // my warp's 2 rows (S phase)
    const int spkt = tid >> 4;                 // packet 0..11 (16B each)
    const int srnk = tid & 15;                 // target rank
    uint32_t rAF4 = 0, rBF4 = 0, rMbAF = 0, rMbEx = 0;
    if (tid < 192) {
        rAF4  = mapa_sh((uint32_t)__cvta_generic_to_shared(&sAF[base + spkt * 4]), srnk);
        rBF4  = mapa_sh((uint32_t)__cvta_generic_to_shared(&sBF[base + spkt * 4]), srnk);
        rMbAF = mapa_sh(mbAF, srnk);
        rMbEx = mapa_sh(mbEx, srnk);
    }

    float at0 = 0.f, at1 = 0.f;
    if (lane == 0) { at0 = AT[r0]; at1 = AT[r0 + 1]; }
    const float btv = (tid < RPC) ? BT[base + tid] : 0.f;

    // Aitken state (per-thread, identical across CTAs)
    float afp = sAF[tid], bfp = sBF[tid];
    float doaf = 0.f, dobf = 0.f;
    bool  have = false;
    int   ph   = 0;

    for (int iter = 0; iter < MAX_ITERS; ++iter) {
        const uint32_t par = iter & 1;
        if (tid == 0) { mbar_expect_tx(mbAF, AF_TX); mbar_expect_tx(mbEx, BF_TX); }

        // ---------------- S phase: AF = AT / (1 + K @ BF), bf16 SMEM ------
        float s0 = 0.f, s1 = 0.f;
        {
            const uint2* kr0 = (const uint2*)sKr + (size_t)(warp * 2) * 192;
            const uint2* kr1 = kr0 + 192;
            const float4* bf4 = (const float4*)sBF;
            #pragma unroll
            for (int t = 0; t < 6; ++t) {
                const int ix = lane + 32 * t;
                const uint2 u0 = kr0[ix];
                const uint2 u1 = kr1[ix];
                const float4 bv = bf4[ix];
                const float2 a0 = bf2f(u0.x), a1 = bf2f(u0.y);
                const float2 b0 = bf2f(u1.x), b1 = bf2f(u1.y);
                s0 += a0.x*bv.x + a0.y*bv.y + a1.x*bv.z + a1.y*bv.w;
                s1 += b0.x*bv.x + b0.y*bv.y + b1.x*bv.z + b1.y*bv.w;
            }
        }
        #pragma unroll
        for (int o = 16; o; o >>= 1) {
            s0 += __shfl_down_sync(0xffffffffu, s0, o);
            s1 += __shfl_down_sync(0xffffffffu, s1, o);
        }
        if (lane == 0) {
            sAF[r0]     = at0 / (1.f + s0);
            sAF[r0 + 1] = at1 / (1.f + s1);
        }
        __syncthreads();
        if (tid < 192)                          // 12 v4 pkts -> each of 16 ranks
            st_async_v4(rAF4, *(const uint4*)&sAF[base + spkt * 4], rMbAF);
        mbar_wait_par(mbAF, par);               // full AF now in sAF
        const float afc = sAF[tid];             // capture BEFORE any BF send

        // ---------------- T phase: BF = BT / (1 + K^T @ AF), bf16 SMEM ----
        float4 acc = make_float4(0.f, 0.f, 0.f, 0.f);
        #pragma unroll
        for (int t = 0; t < 12; ++t) {
            const int i = gg0 + 64 * t;
            const uint2 u = *(const uint2*)(sKc + i * RPC + cq * 4);
            const float a = sAF[i];
            const float2 f0 = bf2f(u.x), f1 = bf2f(u.y);
            acc.x += f0.x * a; acc.y += f0.y * a;
            acc.z += f1.x * a; acc.w += f1.y * a;
        }
        *(float4*)&sTf[gg0 * RPC + cq * 4] = acc;
        __syncthreads();
        {   // stage A: 64 -> 16 partials per column
            const int colA = tid % 48, segA = tid / 48;
            float s = sTf[(segA * 4 + 0) * RPC + colA];
            s += sTf[(segA * 4 + 1) * RPC + colA];
            s += sTf[(segA * 4 + 2) * RPC + colA];
            s += sTf[(segA * 4 + 3) * RPC + colA];
            sT2[segA * RPC + colA] = s;
        }
        __syncthreads();
        if (tid < RPC) {                        // stage B: one thread per column
            float s = 0.f;
            #pragma unroll
            for (int sg = 0; sg < 16; ++sg) s += sT2[sg * RPC + tid];
            sBF[base + tid] = btv / (1.f + s);
        }
        __syncthreads();
        if (tid < 192)
            st_async_v4(rBF4, *(const uint4*)&sBF[base + spkt * 4], rMbEx);
        mbar_wait_par(mbEx, par);               // full BF now in sBF
        const float bfc = sBF[tid];

        // per-thread deltas every iteration (cheap, no reduction)
        const float dnaf = afc - afp, dnbf = bfc - bfp;

        if (par) {
            // ---- odd iters only: redundant deterministic stats + lambda ----
            float dA = fabsf(dnaf), dB = fabsf(dnbf), mA = afc, mB = bfc;
            float pn = 0.f, pd = 0.f;
            if (have) { pn = dnaf*doaf + dnbf*dobf; pd = doaf*doaf + dobf*dobf; }
            #pragma unroll
            for (int o = 16; o; o >>= 1) {
                dA = fmaxf(dA, __shfl_down_sync(0xffffffffu, dA, o));
                dB = fmaxf(dB, __shfl_down_sync(0xffffffffu, dB, o));
                mA = fmaxf(mA, __shfl_down_sync(0xffffffffu, mA, o));
                mB = fmaxf(mB, __shfl_down_sync(0xffffffffu, mB, o));
                pn += __shfl_down_sync(0xffffffffu, pn, o);
                pd += __shfl_down_sync(0xffffffffu, pd, o);
            }
            if (lane == 0) {
                sR[0][warp] = dA; sR[1][warp] = dB; sR[2][warp] = mA;
                sR[3][warp] = mB; sR[4][warp] = pn; sR[5][warp] = pd;
            }
            __syncthreads();
            if (warp < 6) {
                float v = (lane < 24) ? sR[warp][lane] : 0.f;
                if (warp < 4) {
                    #pragma unroll
                    for (int o = 16; o; o >>= 1) v = fmaxf(v, __shfl_down_sync(0xffffffffu, v, o));
                } else {
                    #pragma unroll
                    for (int o = 16; o; o >>= 1) v += __shfl_down_sync(0xffffffffu, v, o);
                }
                if (lane == 0) sFin[warp] = v;
            }
            __syncthreads();
            const float gdA = sFin[0], gdB = sFin[1], gmA = sFin[2], gmB = sFin[3];
            const float lam = (sFin[5] > 1e-30f) ? (sFin[4] / sFin[5]) : 2.f;
            const float bound = kmax * (gdA * gmB + (gmA + gdA) * gdB);
            if (bound <= TOL) break;

            const bool doExt = have && (ph >= 2) && (lam > -0.9f) && (lam < 0.97f);
            if (doExt) {
                const float f = fminf(lam / (1.f - lam), 32.f);
                const float nb = fmaxf(bfc + dnbf * f, 0.f);
                sBF[tid] = nb;                  // only BF propagates (GS structure)
                afp = fmaxf(afc + dnaf * f, 0.f);
                bfp = nb;
                have = false; ph = 0;
                __syncthreads();
                continue;
            }
        }
        afp = afc; bfp = bfc;
        doaf = dnaf; dobf = dnbf;
        have = true; ++ph;
    }

    // ---------------- final differentiable iterate on exact f32 K ----------
    {
        const float* Kr = K + (size_t)r0 * NAB;
        const float* Kc = K + base + cq * 4;
        const int brow  = tid >> 4;
        const int brnk  = tid & 15;
        const uint32_t rAFf = mapa_sh((uint32_t)__cvta_generic_to_shared(&sAF[base + brow]), brnk);

        float s0 = 0.f, s1 = 0.f;
        const float4* bf4 = (const float4*)sBF;
        #pragma unroll
        for (int t = 0; t < 6; ++t) {
            const int ix = lane + 32 * t;
            const float4 bv = bf4[ix];
            const float4 k0 = ((const float4*)(Kr      ))[ix];
            const float4 k1 = ((const float4*)(Kr + NAB))[ix];
            s0 += k0.x*bv.x + k0.y*bv.y + k0.z*bv.z + k0.w*bv.w;
            s1 += k1.x*bv.x + k1.y*bv.y + k1.z*bv.z + k1.w*bv.w;
        }
        #pragma unroll
        for (int o = 16; o; o >>= 1) {
            s0 += __shfl_down_sync(0xffffffffu, s0, o);
            s1 += __shfl_down_sync(0xffffffffu, s1, o);
        }
        if (lane == 0) {
            sAF[r0]     = at0 / (1.f + s0);
            sAF[r0 + 1] = at1 / (1.f + s1);
        }
        __syncthreads();
        st_cl_f32(rAFf, sAF[base + brow]);     // broadcast final AF
        cluster_arrive_wait();

        float4 acc = make_float4(0.f, 0.f, 0.f, 0.f);
        #pragma unroll
        for (int t = 0; t < 12; ++t) {
            const int i = gg0 + 64 * t;
            const float4 kv = *(const float4*)(Kc + (size_t)i * NAB);
            const float a = sAF[i];
            acc.x += kv.x * a; acc.y += kv.y * a;
            acc.z += kv.z * a; acc.w += kv.w * a;
        }
        *(float4*)&sTf[gg0 * RPC + cq * 4] = acc;
        __syncthreads();
        if (tid < RPC) {
            float s = 0.f;
            #pragma unroll
            for (int g = 0; g < 64; ++g) s += sTf[g * RPC + tid];
            g_BF[base + tid] = BT[base + tid] / (1.f + s);
            g_AF[base + tid] = sAF[base + tid];
        }
    }
}

// ---------------------------------------------------------------------------
// GEMV (PDL secondary): prefetches its first W rows into L2 during the solve,
// then waits for the solve, builds c_j = K_ij*AF_i*BF_j in SMEM and streams W.
// Measured ~7.3 TB/s — at the LTS/HBM ceiling.
// ---------------------------------------------------------------------------
__global__ void __launch_bounds__(256)
gemv_kernel(const float* __restrict__ K, const float* __restrict__ W)
{
    __shared__ __align__(16) float sc[NAB];
    const int i    = blockIdx.x;
    const int tid  = threadIdx.x;
    const int lane = tid & 31;
    const int w    = tid >> 5;

    const float* Wb = W + (size_t)i * NAB;
    #pragma unroll
    for (int t = 0; t < 6; ++t) {
        const float* rp = Wb + (size_t)(w + 8 * t) * NCOL;
        if (lane < 24)
            asm volatile("prefetch.global.L2 [%0];" :: "l"(rp + lane * 32));
    }
    cudaGridDependencySynchronize();           // wait for solve's g_AF/g_BF

    const float afi = g_AF[i];
    #pragma unroll
    for (int j = tid; j < NAB; j += 256)
        sc[j] = K[(size_t)i * NAB + j] * afi * g_BF[j];
    __syncthreads();

    const float4* sc4 = (const float4*)sc;
    for (int r = w; r < NY; r += 8) {
        const float4* wr = (const float4*)(Wb + (size_t)r * NCOL);
        float s = 0.f;
        #pragma unroll
        for (int t = 0; t < 6; ++t) {
            const float4 wv = __ldcs(&wr[lane + 32 * t]);
            const float4 cv = sc4[lane + 32 * t];
            s += wv.x * cv.x; s += wv.y * cv.y;
            s += wv.z * cv.z; s += wv.w * cv.w;
        }
        #pragma unroll
        for (int o = 16; o; o >>= 1) s += __shfl_down_sync(0xffffffffu, s, o);
        if (lane == 0) g_part[(size_t)r * NAB + i] = s;
    }
}

__global__ void __launch_bounds__(256)
reduce_kernel(const float* __restrict__ b, float* __restrict__ Y)
{
    const int lane = threadIdx.x & 31;
    const int gw   = blockIdx.x * 8 + (threadIdx.x >> 5);   // 128 warps
    for (int k = gw; k < NY; k += 128) {
        const float* p = &g_part[(size_t)k * NAB];
        float s = 0.f;
        #pragma unroll
        for (int t = 0; t < 24; ++t) s += p[lane + 32 * t];
        #pragma unroll
        for (int o = 16; o; o >>= 1) s += __shfl_down_sync(0xffffffffu, s, o);
        if (lane == 0) Y[k] = s + b[k];
    }
}

extern "C" void kernel_launch(void* const* d_in, const int* in_sizes, int n_in,
                              void* d_out, int out_size)
{
    const float* AT = (const float*)d_in[0];
    const float* BT = (const float*)d_in[1];
    const float* K  = (const float*)d_in[2];
    const float* W  = (const float*)d_in[3];
    const float* b  = (const float*)d_in[4];
    float* Y = (float*)d_out;

    static int attr_done = 0;
    if (!attr_done) {
        cudaFuncSetAttribute((const void*)solve_kernel,
                             cudaFuncAttributeNonPortableClusterSizeAllowed, 1);
        cudaFuncSetAttribute((const void*)solve_kernel,
                             cudaFuncAttributeMaxDynamicSharedMemorySize, DYN_BYTES);
        attr_done = 1;
    }

    // solve: 16-CTA cluster
    cudaLaunchConfig_t cfg = {};
    cfg.gridDim  = {CLUSTER, 1, 1};
    cfg.blockDim = {THREADS, 1, 1};
    cfg.dynamicSmemBytes = DYN_BYTES;
    cfg.stream = 0;
    cudaLaunchAttribute at[1];
    at[0].id = cudaLaunchAttributeClusterDimension;
    at[0].val.clusterDim = {CLUSTER, 1, 1};
    cfg.attrs = at;
    cfg.numAttrs = 1;
    cudaLaunchKernelEx(&cfg, solve_kernel, AT, BT, K);

    // gemv: PDL secondary (launches early; prefetches W; griddepsync gates use)
    cudaLaunchConfig_t g = {};
    g.gridDim  = {NAB, 1, 1};
    g.blockDim = {256, 1, 1};
    g.dynamicSmemBytes = 0;
    g.stream = 0;
    cudaLaunchAttribute ga[1];
    ga[0].id = cudaLaunchAttributeProgrammaticStreamSerialization;
    ga[0].val.programmaticStreamSerializationAllowed = 1;
    g.attrs = ga;
    g.numAttrs = 1;
    cudaLaunchKernelEx(&g, gemv_kernel, K, W);

    reduce_kernel<<<16, 256>>>(b, Y);
}